// round 16
// baseline (speedup 1.0000x reference)
#include <cuda_runtime.h>
#include <cuda_fp16.h>

// Problem constants
#define Bb   128
#define Tt   256
#define Nn   16
#define Kk   10
#define Hh   20
#define BT   32768          // Bb*Tt
#define KT   (Kk*Tt)        // 2560

typedef unsigned long long u64;

// Scratch (static device globals — no allocation)
// Sample index j = t*128 + b (b-fastest)
__device__ float  g_xs[Nn * BT];                   // standardized x, [n][j], 2 MB
__device__ __half g_t [(size_t)Kk * Nn * BT];      // t values fp16, [k][n][j], 10 MB
__device__ float  g_sq[KT];                        // per-(k,t) squared diffs
__device__ unsigned int g_ctr;                     // completion counter (zero-init)

// ---------------- packed f32x2 helpers ----------------
__device__ __forceinline__ u64 pk(float lo, float hi) {
    u64 r; asm("mov.b64 %0,{%1,%2};" : "=l"(r) : "f"(lo), "f"(hi)); return r;
}
__device__ __forceinline__ float2 up(u64 v) {
    float2 f; asm("mov.b64 {%0,%1},%2;" : "=f"(f.x), "=f"(f.y) : "l"(v)); return f;
}
#define FMA2(d,a,b,c) asm("fma.rn.f32x2 %0,%1,%2,%3;" : "=l"(d) : "l"(a), "l"(b), "l"(c))
#define ADD2(d,a,b)   asm("add.rn.f32x2 %0,%1,%2;"    : "=l"(d) : "l"(a), "l"(b))
#define MUL2(d,a,b)   asm("mul.rn.f32x2 %0,%1,%2;"    : "=l"(d) : "l"(a), "l"(b))

__device__ __forceinline__ u64 relu2(u64 v) {
    float2 f = up(v);
    return pk(fmaxf(f.x, 0.f), fmaxf(f.y, 0.f));
}
// pack two f32 into f16x2: low half = lo, high half = hi
__device__ __forceinline__ unsigned int h2pk(float lo, float hi) {
    unsigned int d;
    asm("cvt.rn.f16x2.f32 %0, %1, %2;" : "=r"(d) : "f"(hi), "f"(lo));
    return d;
}

// ---------------------------------------------------------------------------
// Kernel 1: fused standardize (R15 form): stats over b (ddof=1) + normalize +
// transpose x[b][t][n] -> g_xs[n][t*128+b]. grid = 256, 256 threads.
// ---------------------------------------------------------------------------
__global__ void __launch_bounds__(256) std_kernel(const float* __restrict__ x) {
    __shared__ float s[16][132];       // [n][b]
    __shared__ float2 coef[16];        // {ri, -mu*ri}
    int t0 = blockIdx.x;
    int tid = threadIdx.x;

#pragma unroll
    for (int r = 0; r < 2; r++) {
        int f = r * 256 + tid;
        int nq = f & 3, b = f >> 2;
        float4 v = *(const float4*)(x + ((size_t)(b * Tt + t0)) * Nn + nq * 4);
        s[nq * 4 + 0][b] = v.x;
        s[nq * 4 + 1][b] = v.y;
        s[nq * 4 + 2][b] = v.z;
        s[nq * 4 + 3][b] = v.w;
    }
    __syncthreads();

    int col = tid >> 4, sub = tid & 15;
    float S = 0.f, Q = 0.f;
#pragma unroll
    for (int i = 0; i < 8; i++) {
        float v = s[col][sub * 8 + i];
        S += v; Q = fmaf(v, v, Q);
    }
#pragma unroll
    for (int o = 8; o; o >>= 1) {
        S += __shfl_xor_sync(0xffffffffu, S, o);
        Q += __shfl_xor_sync(0xffffffffu, Q, o);
    }
    if (sub == 0) {
        float mu = S * (1.f / 128.f);
        float ri = 1.f / sqrtf((Q - S * mu) * (1.f / 127.f));   // ddof=1, no eps
        coef[col] = make_float2(ri, -mu * ri);
    }
    __syncthreads();

    float2 c = coef[col];
    float* outp = g_xs + col * BT + t0 * 128 + sub * 8;
#pragma unroll
    for (int q = 0; q < 2; q++) {
        float4 o;
        o.x = fmaf(s[col][sub * 8 + q * 4 + 0], c.x, c.y);
        o.y = fmaf(s[col][sub * 8 + q * 4 + 1], c.x, c.y);
        o.z = fmaf(s[col][sub * 8 + q * 4 + 2], c.x, c.y);
        o.w = fmaf(s[col][sub * 8 + q * 4 + 3], c.x, c.y);
        *(float4*)(outp + q * 4) = o;
    }
}

// ---------------------------------------------------------------------------
// Kernel 2: MLP sweep, packed f32x2, P=2 packs (4 samples per thread).
// Lower register pressure (h[2][20]) -> 3 blocks/SM (12 warps) for latency
// hiding; fp16 output (one STG.64 per thread). grid = (K*N, 64), 128 thr.
// ---------------------------------------------------------------------------
__global__ void __launch_bounds__(128, 3) mlp_kernel(
    const float* __restrict__ W1, const float* __restrict__ b1,
    const float* __restrict__ W2, const float* __restrict__ b2,
    const float* __restrict__ W3, const float* __restrict__ b3)
{
    __shared__ __align__(16) float sw2f[Hh][Hh * 2];   // [o][2i..2i+1] = dup W2[o][i]
    __shared__ __align__(16) float sw1b1[Hh][4];       // {w1,w1,b1,b1}
    __shared__ __align__(16) float sb2w3[Hh][4];       // {b2,b2,w3,w3}
    __shared__ __align__(16) float sc[4];              // {w3sum,w3sum,b3,b3}

    int kn = blockIdx.x;          // k*N + n
    int n  = kn & 15;
    int k  = kn >> 4;
    int tid = threadIdx.x;

    for (int idx = tid; idx < Hh * Hh; idx += 128) {
        float v = W2[kn * Hh * Hh + idx];
        int o = idx / Hh, i = idx % Hh;
        sw2f[o][2 * i] = v; sw2f[o][2 * i + 1] = v;
    }
    if (tid < Hh) {
        float w = W1[kn * Hh + tid], b = b1[kn * Hh + tid];
        sw1b1[tid][0] = w; sw1b1[tid][1] = w;
        sw1b1[tid][2] = b; sw1b1[tid][3] = b;
        float bb = b2[kn * Hh + tid];
        float w3 = W3[kn * Hh + tid];
        sb2w3[tid][0] = bb; sb2w3[tid][1] = bb;
        sb2w3[tid][2] = w3; sb2w3[tid][3] = w3;
    }
    if (tid == 0) {
        float s3 = 0.f;
#pragma unroll
        for (int i = 0; i < Hh; i++) s3 += W3[kn * Hh + i];
        sc[0] = s3; sc[1] = s3;
        float bb3 = b3[kn];
        sc[2] = bb3; sc[3] = bb3;
    }
    __syncthreads();

    const float* xs = g_xs + n * BT;
    __half* tout = g_t + (size_t)(k * Nn + n) * BT;

    int j0 = (blockIdx.y * 128 + tid) * 4;
    float4 xa = *(const float4*)(xs + j0);
    u64 xp[2];
    xp[0] = pk(xa.x, xa.y); xp[1] = pk(xa.z, xa.w);

    const u64 ZERO = 0ull;
    const u64 c005  = pk(0.05f, 0.05f);
    const u64 cn005 = pk(-0.05f, -0.05f);

    // ---- layer 1 with streamed LN1 stats ----
    u64 h[2][Hh];
    u64 s1[2], q1[2];
#pragma unroll
    for (int p = 0; p < 2; p++) { s1[p] = ZERO; q1[p] = ZERO; }
#pragma unroll
    for (int i = 0; i < Hh; i++) {
        ulonglong2 wb = *(const ulonglong2*)&sw1b1[i][0];
#pragma unroll
        for (int p = 0; p < 2; p++) {
            u64 t; FMA2(t, xp[p], wb.x, wb.y);
            t = relu2(t);
            h[p][i] = t;
            ADD2(s1[p], s1[p], t);
            FMA2(q1[p], t, t, q1[p]);
        }
    }
    // LN1 in place
#pragma unroll
    for (int p = 0; p < 2; p++) {
        u64 mu, nmu, ex, var;
        MUL2(mu,  s1[p], c005);
        MUL2(nmu, s1[p], cn005);
        MUL2(ex,  q1[p], c005);
        FMA2(var, mu, nmu, ex);     // E[h^2] - mu^2 (biased)
        float2 vf = up(var);
        float rx = rsqrtf(vf.x + 1e-5f);
        float ry = rsqrtf(vf.y + 1e-5f);
        u64 r1 = pk(rx, ry);
        u64 v1; MUL2(v1, nmu, r1);
#pragma unroll
        for (int i = 0; i < Hh; i++)
            FMA2(h[p][i], h[p][i], r1, v1);
    }

    // ---- layer 2; accumulators start at b2; stream LN2 stats + W3 dot ----
    u64 s2[2], q2[2], d3[2];
#pragma unroll
    for (int p = 0; p < 2; p++) { s2[p] = ZERO; q2[p] = ZERO; d3[p] = ZERO; }

#pragma unroll 4
    for (int o = 0; o < Hh; o++) {
        const ulonglong2* wrow = (const ulonglong2*)&sw2f[o][0];
        ulonglong2 bw = *(const ulonglong2*)&sb2w3[o][0];   // {b2 dup, w3 dup}
        u64 a[2];
        a[0] = bw.x; a[1] = bw.x;
#pragma unroll
        for (int q = 0; q < Hh / 2; q++) {
            ulonglong2 wv = wrow[q];
#pragma unroll
            for (int p = 0; p < 2; p++) {
                FMA2(a[p], h[p][2 * q],     wv.x, a[p]);
                FMA2(a[p], h[p][2 * q + 1], wv.y, a[p]);
            }
        }
#pragma unroll
        for (int p = 0; p < 2; p++) {
            u64 h2 = relu2(a[p]);
            ADD2(s2[p], s2[p], h2);
            FMA2(q2[p], h2, h2, q2[p]);
            FMA2(d3[p], h2, bw.y, d3[p]);
        }
    }

    // ---- LN2 fold + head; convert to fp16 and store 8B ----
    u64 w3s = *(const u64*)&sc[0];
    u64 b3d = *(const u64*)&sc[2];
    uint2 outh;
    unsigned int* oh = (unsigned int*)&outh;
#pragma unroll
    for (int p = 0; p < 2; p++) {
        u64 mu2, nmu2, ex2, var2;
        MUL2(mu2,  s2[p], c005);
        MUL2(nmu2, s2[p], cn005);
        MUL2(ex2,  q2[p], c005);
        FMA2(var2, mu2, nmu2, ex2);
        float2 vf = up(var2);
        float rx = rsqrtf(vf.x + 1e-5f);
        float ry = rsqrtf(vf.y + 1e-5f);
        u64 r2 = pk(rx, ry);
        u64 tmp; FMA2(tmp, nmu2, w3s, d3[p]);
        u64 o2;  FMA2(o2, r2, tmp, b3d);
        float2 of = up(o2);
        oh[p] = h2pk(of.x, of.y);
    }
    *(uint2*)(tout + j0) = outh;
}

// ---------------------------------------------------------------------------
// Kernel 3: penalty (R15 form, PB=4). fp16 g_t, dual-plane uint4 warp loads.
// prod_marginals underflows to exactly 0 in fp32, so d^2 = prod_joint^2.
// grid = 640 blocks, 128 threads.
// ---------------------------------------------------------------------------
#define PB 4

__global__ void __launch_bounds__(128) penalty_kernel(float* __restrict__ out) {
    int bid = blockIdx.x;            // 0..639
    int k   = bid >> 6;
    int tt0 = (bid & 63) * PB;

    __shared__ float s[64][132];     // [n*4+dt][b]
    __shared__ float sac[64][2];     // per col: {r, -mu*r}
    __shared__ float part[4];
    __shared__ unsigned int s_last;

    int tid = threadIdx.x;
    int wid = tid >> 5, lane = tid & 31;

    // load: warp-inst = TWO (n,dt) planes (32 lanes x uint4 = 512B contiguous)
#pragma unroll
    for (int pp = 0; pp < 8; pp++) {
        int idx = pp * 4 + wid;              // 0..31 = n*2 + dp
        int n  = idx >> 1;
        int dp = idx & 1;
        const uint4* src = (const uint4*)(g_t +
            ((size_t)(k * 16 + n)) * BT + (tt0 + dp * 2) * 128);
        uint4 v = src[lane];
        int dt   = dp * 2 + (lane >> 4);     // lanes 0-15: first plane
        int boff = (lane & 15) * 8;
        float2 f0 = __half22float2(*(const __half2*)&v.x);
        float2 f1 = __half22float2(*(const __half2*)&v.y);
        float2 f2 = __half22float2(*(const __half2*)&v.z);
        float2 f3 = __half22float2(*(const __half2*)&v.w);
        float* dst = &s[n * 4 + dt][boff];
        dst[0] = f0.x; dst[1] = f0.y; dst[2] = f1.x; dst[3] = f1.y;
        dst[4] = f2.x; dst[5] = f2.y; dst[6] = f3.x; dst[7] = f3.y;
    }
    __syncthreads();

    // fused stats pass: sum + sumsq over b (2 threads per column)
    int col = tid >> 1, hf = tid & 1;
    float S = 0.f, Q = 0.f;
#pragma unroll 8
    for (int i = 0; i < 64; i++) {
        float v = s[col][hf * 64 + i];
        S += v; Q = fmaf(v, v, Q);
    }
    S += __shfl_xor_sync(0xffffffffu, S, 1);
    Q += __shfl_xor_sync(0xffffffffu, Q, 1);
    if (hf == 0) {
        float mu = S * (1.f / 128.f);
        float r  = 1.f / (sqrtf((Q - S * mu) * (1.f / 127.f)) + 1e-8f);
        sac[col][0] = r;
        sac[col][1] = -mu * r;
    }
    __syncthreads();

    // product pass: warp = dt; coefficients in registers (broadcast LDS)
    int dt = wid;
    float2 ac[16];
#pragma unroll
    for (int n = 0; n < 16; n++)
        ac[n] = *(const float2*)&sac[n * 4 + dt][0];

    float acc = 0.f;
#pragma unroll
    for (int j = 0; j < 4; j++) {
        int bb = lane + 32 * j;               // stride-1 lanes: conflict-free
        float prod = fmaf(s[0 * 4 + dt][bb], ac[0].x, ac[0].y);
#pragma unroll
        for (int n = 1; n < 16; n++)
            prod *= fmaf(s[n * 4 + dt][bb], ac[n].x, ac[n].y);
        acc += prod;
    }
#pragma unroll
    for (int o = 16; o; o >>= 1) acc += __shfl_xor_sync(0xffffffffu, acc, o);
    if (lane == 0) {
        float pj = acc * (1.f / 128.f);       // d = 0 - pj; d^2 = pj^2
        g_sq[k * Tt + tt0 + dt] = pj * pj;
    }

    // completion counter: last block reduces g_sq deterministically
    __threadfence();
    __syncthreads();
    if (tid == 0) {
        unsigned int t = atomicAdd(&g_ctr, 1u);
        s_last = (t == (unsigned int)(Kk * Tt / PB - 1)) ? 1u : 0u;
    }
    __syncthreads();
    if (s_last) {
        __threadfence();
        float facc = 0.f;
        for (int i = tid; i < KT; i += 128) facc += g_sq[i];
#pragma unroll
        for (int o = 16; o; o >>= 1) facc += __shfl_xor_sync(0xffffffffu, facc, o);
        if ((tid & 31) == 0) part[tid >> 5] = facc;
        __syncthreads();
        if (tid == 0) {
            out[0] = (part[0] + part[1] + part[2] + part[3]) * (1.f / (float)KT);
            g_ctr = 0u;   // reset for next graph replay
        }
    }
}

// ---------------------------------------------------------------------------
extern "C" void kernel_launch(void* const* d_in, const int* in_sizes, int n_in,
                              void* d_out, int out_size) {
    const float* x  = (const float*)d_in[0];
    const float* W1 = (const float*)d_in[1];
    const float* b1 = (const float*)d_in[2];
    const float* W2 = (const float*)d_in[3];
    const float* b2 = (const float*)d_in[4];
    const float* W3 = (const float*)d_in[5];
    const float* b3 = (const float*)d_in[6];

    std_kernel<<<256, 256>>>(x);

    dim3 g2(Kk * Nn, 64);
    mlp_kernel<<<g2, 128>>>(W1, b1, W2, b2, W3, b3);

    penalty_kernel<<<KT / PB, 128>>>((float*)d_out);
}

// round 17
// speedup vs baseline: 1.1520x; 1.1520x over previous
#include <cuda_runtime.h>
#include <cuda_fp16.h>

// Problem constants
#define Bb   128
#define Tt   256
#define Nn   16
#define Kk   10
#define Hh   20
#define BT   32768          // Bb*Tt
#define KT   (Kk*Tt)        // 2560

typedef unsigned long long u64;

// Scratch (static device globals — no allocation)
// Sample index j = t*128 + b (b-fastest)
__device__ float  g_xs[Nn * BT];                   // standardized x, [n][j], 2 MB
__device__ __half g_t [(size_t)Kk * Nn * BT];      // t values fp16, [k][n][j], 10 MB
__device__ float  g_sq[KT];                        // per-(k,t) squared diffs
__device__ unsigned int g_ctr;                     // completion counter (zero-init)

// ---------------- packed f32x2 helpers ----------------
__device__ __forceinline__ u64 pk(float lo, float hi) {
    u64 r; asm("mov.b64 %0,{%1,%2};" : "=l"(r) : "f"(lo), "f"(hi)); return r;
}
__device__ __forceinline__ float2 up(u64 v) {
    float2 f; asm("mov.b64 {%0,%1},%2;" : "=f"(f.x), "=f"(f.y) : "l"(v)); return f;
}
#define FMA2(d,a,b,c) asm("fma.rn.f32x2 %0,%1,%2,%3;" : "=l"(d) : "l"(a), "l"(b), "l"(c))
#define ADD2(d,a,b)   asm("add.rn.f32x2 %0,%1,%2;"    : "=l"(d) : "l"(a), "l"(b))
#define MUL2(d,a,b)   asm("mul.rn.f32x2 %0,%1,%2;"    : "=l"(d) : "l"(a), "l"(b))

__device__ __forceinline__ u64 relu2(u64 v) {
    float2 f = up(v);
    return pk(fmaxf(f.x, 0.f), fmaxf(f.y, 0.f));
}
// pack two f32 into f16x2: low half = lo, high half = hi
__device__ __forceinline__ unsigned int h2pk(float lo, float hi) {
    unsigned int d;
    asm("cvt.rn.f16x2.f32 %0, %1, %2;" : "=r"(d) : "f"(hi), "f"(lo));
    return d;
}

// ---------------------------------------------------------------------------
// Kernel 1: fused standardize: stats over b (ddof=1) + normalize + transpose
// x[b][t][n] -> g_xs[n][t*128+b]. Block = 1 t x 128 b x 16 n (8 KB tile).
// grid = 256, 256 threads.
// ---------------------------------------------------------------------------
__global__ void __launch_bounds__(256) std_kernel(const float* __restrict__ x) {
    __shared__ float s[16][132];       // [n][b]
    __shared__ float2 coef[16];        // {ri, -mu*ri}
    int t0 = blockIdx.x;
    int tid = threadIdx.x;

#pragma unroll
    for (int r = 0; r < 2; r++) {
        int f = r * 256 + tid;
        int nq = f & 3, b = f >> 2;
        float4 v = *(const float4*)(x + ((size_t)(b * Tt + t0)) * Nn + nq * 4);
        s[nq * 4 + 0][b] = v.x;
        s[nq * 4 + 1][b] = v.y;
        s[nq * 4 + 2][b] = v.z;
        s[nq * 4 + 3][b] = v.w;
    }
    __syncthreads();

    int col = tid >> 4, sub = tid & 15;
    float S = 0.f, Q = 0.f;
#pragma unroll
    for (int i = 0; i < 8; i++) {
        float v = s[col][sub * 8 + i];
        S += v; Q = fmaf(v, v, Q);
    }
#pragma unroll
    for (int o = 8; o; o >>= 1) {
        S += __shfl_xor_sync(0xffffffffu, S, o);
        Q += __shfl_xor_sync(0xffffffffu, Q, o);
    }
    if (sub == 0) {
        float mu = S * (1.f / 128.f);
        float ri = 1.f / sqrtf((Q - S * mu) * (1.f / 127.f));   // ddof=1, no eps
        coef[col] = make_float2(ri, -mu * ri);
    }
    __syncthreads();

    float2 c = coef[col];
    float* outp = g_xs + col * BT + t0 * 128 + sub * 8;
#pragma unroll
    for (int q = 0; q < 2; q++) {
        float4 o;
        o.x = fmaf(s[col][sub * 8 + q * 4 + 0], c.x, c.y);
        o.y = fmaf(s[col][sub * 8 + q * 4 + 1], c.x, c.y);
        o.z = fmaf(s[col][sub * 8 + q * 4 + 2], c.x, c.y);
        o.w = fmaf(s[col][sub * 8 + q * 4 + 3], c.x, c.y);
        *(float4*)(outp + q * 4) = o;
    }
}

// ---------------------------------------------------------------------------
// Kernel 2: MLP sweep, packed f32x2, 8 samples per thread (4 packed pairs).
// xs global loads issued BEFORE the weight fill (overlap DRAM latency with
// weight LDG/STS). fp16 output (one STG.128/thread). grid = (K*N, 32).
// ---------------------------------------------------------------------------
__global__ void __launch_bounds__(128) mlp_kernel(
    const float* __restrict__ W1, const float* __restrict__ b1,
    const float* __restrict__ W2, const float* __restrict__ b2,
    const float* __restrict__ W3, const float* __restrict__ b3)
{
    __shared__ __align__(16) float sw2f[Hh][Hh * 2];   // [o][2i..2i+1] = dup W2[o][i]
    __shared__ __align__(16) float sw1b1[Hh][4];       // {w1,w1,b1,b1}
    __shared__ __align__(16) float sb2w3[Hh][4];       // {b2,b2,w3,w3}
    __shared__ __align__(16) float sc[4];              // {w3sum,w3sum,b3,b3}

    int kn = blockIdx.x;          // k*N + n
    int n  = kn & 15;
    int k  = kn >> 4;
    int tid = threadIdx.x;

    // ---- issue x loads FIRST (independent of smem; hides DRAM latency) ----
    const float* xs = g_xs + n * BT;
    int j0 = (blockIdx.y * 128 + tid) * 8;
    float4 xa = *(const float4*)(xs + j0);
    float4 xb = *(const float4*)(xs + j0 + 4);

    // ---- weight fill (overlaps with outstanding x loads) ----
    for (int idx = tid; idx < Hh * Hh; idx += 128) {
        float v = W2[kn * Hh * Hh + idx];
        int o = idx / Hh, i = idx % Hh;
        sw2f[o][2 * i] = v; sw2f[o][2 * i + 1] = v;
    }
    if (tid < Hh) {
        float w = W1[kn * Hh + tid], b = b1[kn * Hh + tid];
        sw1b1[tid][0] = w; sw1b1[tid][1] = w;
        sw1b1[tid][2] = b; sw1b1[tid][3] = b;
        float bb = b2[kn * Hh + tid];
        float w3 = W3[kn * Hh + tid];
        sb2w3[tid][0] = bb; sb2w3[tid][1] = bb;
        sb2w3[tid][2] = w3; sb2w3[tid][3] = w3;
    }
    if (tid == 0) {
        float s3 = 0.f;
#pragma unroll
        for (int i = 0; i < Hh; i++) s3 += W3[kn * Hh + i];
        sc[0] = s3; sc[1] = s3;
        float bb3 = b3[kn];
        sc[2] = bb3; sc[3] = bb3;
    }
    __syncthreads();

    __half* tout = g_t + (size_t)(k * Nn + n) * BT;

    u64 xp[4];
    xp[0] = pk(xa.x, xa.y); xp[1] = pk(xa.z, xa.w);
    xp[2] = pk(xb.x, xb.y); xp[3] = pk(xb.z, xb.w);

    const u64 ZERO = 0ull;
    const u64 c005  = pk(0.05f, 0.05f);
    const u64 cn005 = pk(-0.05f, -0.05f);

    // ---- layer 1 with streamed LN1 stats ----
    u64 h[4][Hh];
    u64 s1[4], q1[4];
#pragma unroll
    for (int p = 0; p < 4; p++) { s1[p] = ZERO; q1[p] = ZERO; }
#pragma unroll
    for (int i = 0; i < Hh; i++) {
        ulonglong2 wb = *(const ulonglong2*)&sw1b1[i][0];
#pragma unroll
        for (int p = 0; p < 4; p++) {
            u64 t; FMA2(t, xp[p], wb.x, wb.y);
            t = relu2(t);
            h[p][i] = t;
            ADD2(s1[p], s1[p], t);
            FMA2(q1[p], t, t, q1[p]);
        }
    }
    // LN1 in place
#pragma unroll
    for (int p = 0; p < 4; p++) {
        u64 mu, nmu, ex, var;
        MUL2(mu,  s1[p], c005);
        MUL2(nmu, s1[p], cn005);
        MUL2(ex,  q1[p], c005);
        FMA2(var, mu, nmu, ex);     // E[h^2] - mu^2 (biased)
        float2 vf = up(var);
        float rx = rsqrtf(vf.x + 1e-5f);
        float ry = rsqrtf(vf.y + 1e-5f);
        u64 r1 = pk(rx, ry);
        u64 v1; MUL2(v1, nmu, r1);
#pragma unroll
        for (int i = 0; i < Hh; i++)
            FMA2(h[p][i], h[p][i], r1, v1);
    }

    // ---- layer 2; accumulators start at b2; stream LN2 stats + W3 dot ----
    u64 s2[4], q2[4], d3[4];
#pragma unroll
    for (int p = 0; p < 4; p++) { s2[p] = ZERO; q2[p] = ZERO; d3[p] = ZERO; }

#pragma unroll 4
    for (int o = 0; o < Hh; o++) {
        const ulonglong2* wrow = (const ulonglong2*)&sw2f[o][0];
        ulonglong2 bw = *(const ulonglong2*)&sb2w3[o][0];   // {b2 dup, w3 dup}
        u64 a[4];
        a[0] = bw.x; a[1] = bw.x; a[2] = bw.x; a[3] = bw.x;
#pragma unroll
        for (int q = 0; q < Hh / 2; q++) {
            ulonglong2 wv = wrow[q];
#pragma unroll
            for (int p = 0; p < 4; p++) {
                FMA2(a[p], h[p][2 * q],     wv.x, a[p]);
                FMA2(a[p], h[p][2 * q + 1], wv.y, a[p]);
            }
        }
#pragma unroll
        for (int p = 0; p < 4; p++) {
            u64 h2 = relu2(a[p]);
            ADD2(s2[p], s2[p], h2);
            FMA2(q2[p], h2, h2, q2[p]);
            FMA2(d3[p], h2, bw.y, d3[p]);
        }
    }

    // ---- LN2 fold + head; convert to fp16 and store 16B ----
    u64 w3s = *(const u64*)&sc[0];
    u64 b3d = *(const u64*)&sc[2];
    uint4 outh;
    unsigned int* oh = (unsigned int*)&outh;
#pragma unroll
    for (int p = 0; p < 4; p++) {
        u64 mu2, nmu2, ex2, var2;
        MUL2(mu2,  s2[p], c005);
        MUL2(nmu2, s2[p], cn005);
        MUL2(ex2,  q2[p], c005);
        FMA2(var2, mu2, nmu2, ex2);
        float2 vf = up(var2);
        float rx = rsqrtf(vf.x + 1e-5f);
        float ry = rsqrtf(vf.y + 1e-5f);
        u64 r2 = pk(rx, ry);
        u64 tmp; FMA2(tmp, nmu2, w3s, d3[p]);
        u64 o2;  FMA2(o2, r2, tmp, b3d);
        float2 of = up(o2);
        oh[p] = h2pk(of.x, of.y);
    }
    *(uint4*)(tout + j0) = outh;
}

// ---------------------------------------------------------------------------
// Kernel 3: penalty (PB=4). fp16 g_t, dual-plane uint4 warp loads (512B).
// prod_marginals underflows to exactly 0 in fp32, so d^2 = prod_joint^2.
// grid = 640 blocks, 128 threads.
// ---------------------------------------------------------------------------
#define PB 4

__global__ void __launch_bounds__(128) penalty_kernel(float* __restrict__ out) {
    int bid = blockIdx.x;            // 0..639
    int k   = bid >> 6;
    int tt0 = (bid & 63) * PB;

    __shared__ float s[64][132];     // [n*4+dt][b]
    __shared__ float sac[64][2];     // per col: {r, -mu*r}
    __shared__ float part[4];
    __shared__ unsigned int s_last;

    int tid = threadIdx.x;
    int wid = tid >> 5, lane = tid & 31;

    // load: warp-inst = TWO (n,dt) planes (32 lanes x uint4 = 512B contiguous)
#pragma unroll
    for (int pp = 0; pp < 8; pp++) {
        int idx = pp * 4 + wid;              // 0..31 = n*2 + dp
        int n  = idx >> 1;
        int dp = idx & 1;
        const uint4* src = (const uint4*)(g_t +
            ((size_t)(k * 16 + n)) * BT + (tt0 + dp * 2) * 128);
        uint4 v = src[lane];
        int dt   = dp * 2 + (lane >> 4);     // lanes 0-15: first plane
        int boff = (lane & 15) * 8;
        float2 f0 = __half22float2(*(const __half2*)&v.x);
        float2 f1 = __half22float2(*(const __half2*)&v.y);
        float2 f2 = __half22float2(*(const __half2*)&v.z);
        float2 f3 = __half22float2(*(const __half2*)&v.w);
        float* dst = &s[n * 4 + dt][boff];
        dst[0] = f0.x; dst[1] = f0.y; dst[2] = f1.x; dst[3] = f1.y;
        dst[4] = f2.x; dst[5] = f2.y; dst[6] = f3.x; dst[7] = f3.y;
    }
    __syncthreads();

    // fused stats pass: sum + sumsq over b (2 threads per column)
    int col = tid >> 1, hf = tid & 1;
    float S = 0.f, Q = 0.f;
#pragma unroll 8
    for (int i = 0; i < 64; i++) {
        float v = s[col][hf * 64 + i];
        S += v; Q = fmaf(v, v, Q);
    }
    S += __shfl_xor_sync(0xffffffffu, S, 1);
    Q += __shfl_xor_sync(0xffffffffu, Q, 1);
    if (hf == 0) {
        float mu = S * (1.f / 128.f);
        float r  = 1.f / (sqrtf((Q - S * mu) * (1.f / 127.f)) + 1e-8f);
        sac[col][0] = r;
        sac[col][1] = -mu * r;
    }
    __syncthreads();

    // product pass: warp = dt; coefficients in registers (broadcast LDS)
    int dt = wid;
    float2 ac[16];
#pragma unroll
    for (int n = 0; n < 16; n++)
        ac[n] = *(const float2*)&sac[n * 4 + dt][0];

    float acc = 0.f;
#pragma unroll
    for (int j = 0; j < 4; j++) {
        int bb = lane + 32 * j;               // stride-1 lanes: conflict-free
        float prod = fmaf(s[0 * 4 + dt][bb], ac[0].x, ac[0].y);
#pragma unroll
        for (int n = 1; n < 16; n++)
            prod *= fmaf(s[n * 4 + dt][bb], ac[n].x, ac[n].y);
        acc += prod;
    }
#pragma unroll
    for (int o = 16; o; o >>= 1) acc += __shfl_xor_sync(0xffffffffu, acc, o);
    if (lane == 0) {
        float pj = acc * (1.f / 128.f);       // d = 0 - pj; d^2 = pj^2
        g_sq[k * Tt + tt0 + dt] = pj * pj;
    }

    // completion counter: last block reduces g_sq deterministically
    __threadfence();
    __syncthreads();
    if (tid == 0) {
        unsigned int t = atomicAdd(&g_ctr, 1u);
        s_last = (t == (unsigned int)(Kk * Tt / PB - 1)) ? 1u : 0u;
    }
    __syncthreads();
    if (s_last) {
        __threadfence();
        float facc = 0.f;
        for (int i = tid; i < KT; i += 128) facc += g_sq[i];
#pragma unroll
        for (int o = 16; o; o >>= 1) facc += __shfl_xor_sync(0xffffffffu, facc, o);
        if ((tid & 31) == 0) part[tid >> 5] = facc;
        __syncthreads();
        if (tid == 0) {
            out[0] = (part[0] + part[1] + part[2] + part[3]) * (1.f / (float)KT);
            g_ctr = 0u;   // reset for next graph replay
        }
    }
}

// ---------------------------------------------------------------------------
extern "C" void kernel_launch(void* const* d_in, const int* in_sizes, int n_in,
                              void* d_out, int out_size) {
    const float* x  = (const float*)d_in[0];
    const float* W1 = (const float*)d_in[1];
    const float* b1 = (const float*)d_in[2];
    const float* W2 = (const float*)d_in[3];
    const float* b2 = (const float*)d_in[4];
    const float* W3 = (const float*)d_in[5];
    const float* b3 = (const float*)d_in[6];

    std_kernel<<<256, 256>>>(x);

    dim3 g2(Kk * Nn, 32);
    mlp_kernel<<<g2, 128>>>(W1, b1, W2, b2, W3, b3);

    penalty_kernel<<<KT / PB, 128>>>((float*)d_out);
}